// round 1
// baseline (speedup 1.0000x reference)
#include <cuda_runtime.h>
#include <cstdint>
#include <cstddef>

#define MM    3
#define NN    100000
#define DIN   128
#define DH    64
#define EDGES 1600000

// ---------------- scratch (device globals; no allocations) ----------------
__device__ float g_proj[(size_t)MM * NN * DH];   // 76.8 MB  [m][n][h]
__device__ float g_agg [(size_t)MM * NN * DH];   // 76.8 MB  [m][n][h]
__device__ float g_hn  [(size_t)NN * MM * DH];   // 76.8 MB  [n][m][h]
__device__ float g_deg [(size_t)MM * NN];        // 1.2  MB
__device__ float g_logits[MM];

// packed f32x2 FMA (FFMA2) — 2x fp32 FMA throughput, only reachable via PTX
__device__ __forceinline__ float2 ffma2(float2 a, float2 b, float2 c) {
    unsigned long long au = *reinterpret_cast<unsigned long long*>(&a);
    unsigned long long bu = *reinterpret_cast<unsigned long long*>(&b);
    unsigned long long cu = *reinterpret_cast<unsigned long long*>(&c);
    unsigned long long du;
    asm("fma.rn.f32x2 %0, %1, %2, %3;" : "=l"(du) : "l"(au), "l"(bu), "l"(cu));
    return *reinterpret_cast<float2*>(&du);
}

// ---------------- K1: proj[m] = feats[m] @ W[m] ----------------
// block = 256 threads, covers 256 nodes. thread tile: 4 nodes x 16 h (8 f32x2 pairs).
// h(j) = 2*(hg + 4*j), hg = tid&3, j = 0..7  -> conflict-free smem W reads.
__global__ __launch_bounds__(256) void k_proj(const float* __restrict__ feats,
                                              const float* __restrict__ W) {
    __shared__ float sF[256][33];   // 256 nodes x 32-k tile, padded
    __shared__ float sW[32][64];    // 32-k x 64-h tile

    const int m     = blockIdx.y;
    const int node0 = blockIdx.x * 256;
    const int t  = threadIdx.x;
    const int hg = t & 3;
    const int ng = t >> 2;               // 0..63
    const int nbase = node0 + ng * 4;

    const float* fbase = feats + (size_t)m * NN * DIN;
    const float* wbase = W     + (size_t)m * DIN * DH;

    float2 acc[4][8];
    #pragma unroll
    for (int i = 0; i < 4; i++)
        #pragma unroll
        for (int j = 0; j < 8; j++) acc[i][j] = make_float2(0.f, 0.f);

    for (int kt = 0; kt < DIN; kt += 32) {
        __syncthreads();
        // feats tile: 256 rows x 32 cols = 2048 float4 / 256 threads = 8 each
        #pragma unroll
        for (int it = 0; it < 8; it++) {
            int idx  = t + 256 * it;
            int row  = idx >> 3;
            int c4   = idx & 7;
            int gn   = node0 + row;
            float4 v = make_float4(0.f, 0.f, 0.f, 0.f);
            if (gn < NN)
                v = *(const float4*)(fbase + (size_t)gn * DIN + kt + c4 * 4);
            sF[row][c4*4+0] = v.x; sF[row][c4*4+1] = v.y;
            sF[row][c4*4+2] = v.z; sF[row][c4*4+3] = v.w;
        }
        // W tile: 32 rows x 64 cols = 512 float4 / 256 threads = 2 each
        #pragma unroll
        for (int it = 0; it < 2; it++) {
            int idx = t + 256 * it;
            int row = idx >> 4;
            int h4  = idx & 15;
            *(float4*)&sW[row][h4*4] =
                *(const float4*)(wbase + (size_t)(kt + row) * DH + h4 * 4);
        }
        __syncthreads();

        #pragma unroll 4
        for (int k = 0; k < 32; k++) {
            float f0 = sF[ng*4+0][k];
            float f1 = sF[ng*4+1][k];
            float f2 = sF[ng*4+2][k];
            float f3 = sF[ng*4+3][k];
            const float2* wrow = (const float2*)&sW[k][0];
            #pragma unroll
            for (int j = 0; j < 8; j++) {
                float2 wv = wrow[hg + 4*j];
                acc[0][j] = ffma2(make_float2(f0, f0), wv, acc[0][j]);
                acc[1][j] = ffma2(make_float2(f1, f1), wv, acc[1][j]);
                acc[2][j] = ffma2(make_float2(f2, f2), wv, acc[2][j]);
                acc[3][j] = ffma2(make_float2(f3, f3), wv, acc[3][j]);
            }
        }
    }

    float* pbase = g_proj + (size_t)m * NN * DH;
    #pragma unroll
    for (int i = 0; i < 4; i++) {
        int n = nbase + i;
        if (n < NN) {
            float* prow = pbase + (size_t)n * DH;
            #pragma unroll
            for (int j = 0; j < 8; j++)
                *(float2*)(prow + 2 * (hg + 4 * j)) = acc[i][j];
        }
    }
}

// ---------------- K2: edge gather + vec4 reduce-add scatter ----------------
// 16 lanes per edge; each lane moves one float4. grid.y = m.
__global__ void k_edges(const int* __restrict__ src, const int* __restrict__ dst) {
    const int  m      = blockIdx.y;
    const long tid    = (long)blockIdx.x * blockDim.x + threadIdx.x;
    const long e      = tid >> 4;
    const int  lane16 = threadIdx.x & 15;
    if (e >= EDGES) return;

    const int s = __ldg(src + (size_t)m * EDGES + e);
    const int d = __ldg(dst + (size_t)m * EDGES + e);

    float4 v = *((const float4*)(g_proj + ((size_t)m * NN + s) * DH) + lane16);
    float* pdst = g_agg + ((size_t)m * NN + d) * DH + lane16 * 4;
    asm volatile("red.global.add.v4.f32 [%0], {%1,%2,%3,%4};"
                 :: "l"(pdst), "f"(v.x), "f"(v.y), "f"(v.z), "f"(v.w)
                 : "memory");
    if (lane16 == 0)
        atomicAdd(g_deg + (size_t)m * NN + d, 1.0f);
}

// ---------------- K3: h = prelu(agg/deg + b), transpose to [n][m][h] -------
__global__ void k_finalize(const float* __restrict__ b,
                           const float* __restrict__ prelu_a) {
    const long tid = (long)blockIdx.x * blockDim.x + threadIdx.x;
    if (tid >= (long)NN * MM * 16) return;
    const int h4 = (int)(tid & 15);
    const int m  = (int)((tid >> 4) % 3);
    const long n = tid / 48;

    float4 a  = *(const float4*)(g_agg + ((size_t)m * NN + n) * DH + h4 * 4);
    float  dg = g_deg[(size_t)m * NN + n];
    float  inv = 1.0f / fmaxf(dg, 1.0f);
    float  alpha = __ldg(prelu_a + m);
    float4 bv = *(const float4*)(b + m * DH + h4 * 4);

    float4 h;
    h.x = a.x * inv + bv.x;  h.x = h.x > 0.f ? h.x : alpha * h.x;
    h.y = a.y * inv + bv.y;  h.y = h.y > 0.f ? h.y : alpha * h.y;
    h.z = a.z * inv + bv.z;  h.z = h.z > 0.f ? h.z : alpha * h.z;
    h.w = a.w * inv + bv.w;  h.w = h.w > 0.f ? h.w : alpha * h.w;

    *(float4*)(g_hn + ((size_t)n * MM + m) * DH + h4 * 4) = h;
}

// ---------------- K4: logits[m] += sum_n tanh(h @ fcW + fcb) . attn / N ----
// 64 threads per block, one (n,m) row per thread; fcW broadcast from smem.
__global__ __launch_bounds__(64) void k_attnlogits(const float* __restrict__ fc_W,
                                                   const float* __restrict__ fc_b,
                                                   const float* __restrict__ attn) {
    __shared__ float sW[64][64];    // 16 KB
    __shared__ float sH[64][65];    // 16.6 KB (padded: conflict-free per-lane rows)
    __shared__ float sPart[3];

    const int t = threadIdx.x;
    const long p0 = (long)blockIdx.x * 64;

    // load fc_W (flat, coalesced)
    #pragma unroll
    for (int it = 0; it < 16; it++)
        ((float4*)&sW[0][0])[t + 64 * it] = ((const float4*)fc_W)[t + 64 * it];

    // load 64 hn rows (each warp loads 32 rows, coalesced scalar)
    {
        const int warp = t >> 5, lane = t & 31;
        for (int r = warp * 32; r < warp * 32 + 32; r++) {
            long p = p0 + r;
            if (p < (long)NN * MM) {
                sH[r][lane]      = g_hn[(size_t)p * DH + lane];
                sH[r][lane + 32] = g_hn[(size_t)p * DH + lane + 32];
            }
        }
    }
    if (t < 3) sPart[t] = 0.f;
    __syncthreads();

    const long p = p0 + t;
    const bool active = p < (long)NN * MM;
    int myM = 0;
    float part = 0.f;

    if (active) {
        myM = (int)(p % 3);
        float2 acc[32];
        #pragma unroll
        for (int j = 0; j < 32; j++) acc[j] = make_float2(0.f, 0.f);

        #pragma unroll 8
        for (int i = 0; i < 64; i++) {
            float hi = sH[t][i];
            float2 h2 = make_float2(hi, hi);
            const float2* wr = (const float2*)&sW[i][0];
            #pragma unroll
            for (int j = 0; j < 32; j++) acc[j] = ffma2(h2, wr[j], acc[j]);
        }
        #pragma unroll
        for (int j = 0; j < 32; j++) {
            float2 bb = __ldg((const float2*)fc_b + j);
            float2 av = __ldg((const float2*)attn + j);
            float sx = tanhf(acc[j].x + bb.x);
            float sy = tanhf(acc[j].y + bb.y);
            part += sx * av.x + sy * av.y;
        }
    }
    atomicAdd(&sPart[myM], part);
    __syncthreads();
    if (t < 3) atomicAdd(&g_logits[t], sPart[t] * (1.0f / (float)NN));
}

// ---------------- K5: softmax(logits) + z = sum_m beta_m * hn[:,m,:] -------
__global__ void k_combine(float* __restrict__ out) {
    const long tid = (long)blockIdx.x * blockDim.x + threadIdx.x;
    if (tid >= (long)NN * 16) return;
    const int  h4 = (int)(tid & 15);
    const long n  = tid >> 4;

    float l0 = g_logits[0], l1 = g_logits[1], l2 = g_logits[2];
    float mx = fmaxf(l0, fmaxf(l1, l2));
    float e0 = __expf(l0 - mx), e1 = __expf(l1 - mx), e2 = __expf(l2 - mx);
    float is = 1.0f / (e0 + e1 + e2);
    float b0 = e0 * is, b1 = e1 * is, b2 = e2 * is;

    const float4* r = (const float4*)(g_hn + (size_t)n * (MM * DH)) + h4;
    float4 v0 = r[0], v1 = r[16], v2 = r[32];
    float4 o;
    o.x = b0 * v0.x + b1 * v1.x + b2 * v2.x;
    o.y = b0 * v0.y + b1 * v1.y + b2 * v2.y;
    o.z = b0 * v0.z + b1 * v1.z + b2 * v2.z;
    o.w = b0 * v0.w + b1 * v1.w + b2 * v2.w;
    ((float4*)out)[tid] = o;
}

// ---------------- launcher ----------------
extern "C" void kernel_launch(void* const* d_in, const int* in_sizes, int n_in,
                              void* d_out, int out_size) {
    const float* feats   = (const float*)d_in[0];
    const int*   src     = (const int*)  d_in[1];
    const int*   dst     = (const int*)  d_in[2];
    const float* W       = (const float*)d_in[3];
    const float* b       = (const float*)d_in[4];
    const float* prelu_a = (const float*)d_in[5];
    const float* fc_W    = (const float*)d_in[6];
    const float* fc_b    = (const float*)d_in[7];
    const float* attn    = (const float*)d_in[8];
    float* out = (float*)d_out;

    void *p_agg, *p_deg, *p_log;
    cudaGetSymbolAddress(&p_agg, g_agg);
    cudaGetSymbolAddress(&p_deg, g_deg);
    cudaGetSymbolAddress(&p_log, g_logits);
    cudaMemsetAsync(p_agg, 0, sizeof(float) * (size_t)MM * NN * DH, 0);
    cudaMemsetAsync(p_deg, 0, sizeof(float) * (size_t)MM * NN, 0);
    cudaMemsetAsync(p_log, 0, sizeof(float) * MM, 0);

    dim3 g1((NN + 255) / 256, MM);
    k_proj<<<g1, 256>>>(feats, W);

    dim3 g2((int)(((long)EDGES * 16 + 255) / 256), MM);   // 100000 x 3
    k_edges<<<g2, 256>>>(src, dst);

    long t3 = (long)NN * MM * 16;
    k_finalize<<<(unsigned)((t3 + 255) / 256), 256>>>(b, prelu_a);

    k_attnlogits<<<(unsigned)(((long)NN * MM + 63) / 64), 64>>>(fc_W, fc_b, attn);

    k_combine<<<(unsigned)(((long)NN * 16 + 255) / 256), 256>>>(out);
}

// round 2
// speedup vs baseline: 1.4453x; 1.4453x over previous
#include <cuda_runtime.h>
#include <cstdint>
#include <cstddef>

#define MM    3
#define NN    100000
#define DIN   128
#define DH    64
#define EDGES 1600000
#define NSEG  (MM * NN)                 // 300000 segments (m, dst)
#define SCAN_TILE 1024
#define NBLK  ((NSEG + SCAN_TILE - 1) / SCAN_TILE)   // 293

// ---------------- scratch (device globals; no allocations) ----------------
__device__ float g_proj[(size_t)MM * NN * DH];   // 76.8 MB  [m][n][h]
__device__ float g_hn  [(size_t)NN * MM * DH];   // 76.8 MB  [n][m][h]
__device__ int   g_count [NSEG];                 // per-(m,dst) degree
__device__ int   g_cursor[NSEG];                 // excl offsets -> ends after scatter
__device__ int   g_eidx[(size_t)MM * EDGES];     // src ids sorted by (m,dst)
__device__ int   g_bsum[NBLK];
__device__ float g_logits[MM];

// packed f32x2 FMA (FFMA2) — 2x fp32 FMA throughput, only reachable via PTX
__device__ __forceinline__ float2 ffma2(float2 a, float2 b, float2 c) {
    unsigned long long au = *reinterpret_cast<unsigned long long*>(&a);
    unsigned long long bu = *reinterpret_cast<unsigned long long*>(&b);
    unsigned long long cu = *reinterpret_cast<unsigned long long*>(&c);
    unsigned long long du;
    asm("fma.rn.f32x2 %0, %1, %2, %3;" : "=l"(du) : "l"(au), "l"(bu), "l"(cu));
    return *reinterpret_cast<float2*>(&du);
}

// ---------------- K1: proj[m] = feats[m] @ W[m] ----------------
// 128 threads, 256 rows/block. Thread tile: 8 rows (stride 32) x 16 cols.
// rg = t>>2 (0..31), cg = t&3. Row stride 32 => conflict-free sF reads.
#define FPAD 36
__global__ __launch_bounds__(128) void k_proj(const float* __restrict__ feats,
                                              const float* __restrict__ W) {
    __shared__ float sF[256 * FPAD];   // 36 KB (32-k tile, padded rows)
    __shared__ float sW[32 * 64];      // 8 KB

    const int m     = blockIdx.y;
    const int node0 = blockIdx.x * 256;
    const int t  = threadIdx.x;
    const int rg = t >> 2;
    const int cg = t & 3;

    const float* fbase = feats + (size_t)m * NN * DIN;
    const float* wbase = W     + (size_t)m * DIN * DH;

    float2 acc[8][8];
    #pragma unroll
    for (int i = 0; i < 8; i++)
        #pragma unroll
        for (int j = 0; j < 8; j++) acc[i][j] = make_float2(0.f, 0.f);

    for (int kt = 0; kt < DIN; kt += 32) {
        __syncthreads();
        // feats tile: 256 rows x 32 k = 2048 float4 / 128 thr = 16 each
        #pragma unroll
        for (int it = 0; it < 16; it++) {
            int idx = t + 128 * it;
            int row = idx >> 3;
            int k4  = idx & 7;
            int gn  = node0 + row;
            float4 v = make_float4(0.f, 0.f, 0.f, 0.f);
            if (gn < NN)
                v = *(const float4*)(fbase + (size_t)gn * DIN + kt + k4 * 4);
            *(float4*)&sF[row * FPAD + k4 * 4] = v;
        }
        // W slice rows kt..kt+31: flat 512 float4 / 128 thr = 4 each
        #pragma unroll
        for (int it = 0; it < 4; it++) {
            int idx = t + 128 * it;
            ((float4*)sW)[idx] = ((const float4*)(wbase + (size_t)kt * DH))[idx];
        }
        __syncthreads();

        #pragma unroll
        for (int k = 0; k < 32; k++) {
            float f[8];
            #pragma unroll
            for (int i = 0; i < 8; i++) f[i] = sF[(rg + 32 * i) * FPAD + k];
            float4 w0 = *(const float4*)&sW[k * 64 + cg * 16 + 0];
            float4 w1 = *(const float4*)&sW[k * 64 + cg * 16 + 4];
            float4 w2 = *(const float4*)&sW[k * 64 + cg * 16 + 8];
            float4 w3 = *(const float4*)&sW[k * 64 + cg * 16 + 12];
            float2 wv[8] = { {w0.x,w0.y},{w0.z,w0.w},{w1.x,w1.y},{w1.z,w1.w},
                             {w2.x,w2.y},{w2.z,w2.w},{w3.x,w3.y},{w3.z,w3.w} };
            #pragma unroll
            for (int i = 0; i < 8; i++) {
                float2 fi = make_float2(f[i], f[i]);
                #pragma unroll
                for (int j = 0; j < 8; j++)
                    acc[i][j] = ffma2(fi, wv[j], acc[i][j]);
            }
        }
    }

    float* pbase = g_proj + (size_t)m * NN * DH;
    #pragma unroll
    for (int i = 0; i < 8; i++) {
        int n = node0 + rg + 32 * i;
        if (n < NN) {
            float* prow = pbase + (size_t)n * DH + cg * 16;
            #pragma unroll
            for (int j = 0; j < 4; j++)
                *(float4*)(prow + 4 * j) =
                    make_float4(acc[i][2*j].x, acc[i][2*j].y,
                                acc[i][2*j+1].x, acc[i][2*j+1].y);
        }
    }
}

// ---------------- E1: histogram of (m, dst) ----------------
__global__ void k_hist(const int* __restrict__ dst) {
    long tid = (long)blockIdx.x * blockDim.x + threadIdx.x;
    if (tid >= (long)MM * EDGES) return;
    int m = (int)(tid / EDGES);
    int d = dst[tid];
    atomicAdd(&g_count[m * NN + d], 1);
}

// ---------------- E2: 3-phase exclusive scan of g_count -> g_cursor -------
__global__ __launch_bounds__(256) void k_scanA() {
    __shared__ int wsum[8];
    const int t = threadIdx.x;
    const long base = (long)blockIdx.x * SCAN_TILE + t * 4;
    int v[4];
    #pragma unroll
    for (int i = 0; i < 4; i++) v[i] = (base + i < NSEG) ? g_count[base + i] : 0;
    int tsum = v[0] + v[1] + v[2] + v[3];

    const int lane = t & 31, w = t >> 5;
    int x = tsum;
    #pragma unroll
    for (int o = 1; o < 32; o <<= 1) {
        int y = __shfl_up_sync(0xffffffffu, x, o);
        if (lane >= o) x += y;
    }
    if (lane == 31) wsum[w] = x;
    __syncthreads();
    if (t < 8) {
        int y = wsum[t];
        #pragma unroll
        for (int o = 1; o < 8; o <<= 1) {
            int z = __shfl_up_sync(0x000000ffu, y, o);
            if (t >= o) y += z;
        }
        wsum[t] = y;
    }
    __syncthreads();
    int run = ((w > 0) ? wsum[w - 1] : 0) + x - tsum;   // exclusive, within block
    #pragma unroll
    for (int i = 0; i < 4; i++) {
        if (base + i < NSEG) g_cursor[base + i] = run;
        run += v[i];
    }
    if (t == 255) g_bsum[blockIdx.x] = wsum[7];
}

__global__ __launch_bounds__(512) void k_scanB() {
    __shared__ int a[512];
    const int t = threadIdx.x;
    int v = (t < NBLK) ? g_bsum[t] : 0;
    a[t] = v;
    __syncthreads();
    #pragma unroll
    for (int o = 1; o < 512; o <<= 1) {
        int x = (t >= o) ? a[t - o] : 0;
        __syncthreads();
        a[t] += x;
        __syncthreads();
    }
    if (t < NBLK) g_bsum[t] = a[t] - v;    // exclusive
}

__global__ __launch_bounds__(256) void k_scanC() {
    const int add = g_bsum[blockIdx.x];
    const long base = (long)blockIdx.x * SCAN_TILE + threadIdx.x * 4;
    #pragma unroll
    for (int i = 0; i < 4; i++)
        if (base + i < NSEG) g_cursor[base + i] += add;
}

// ---------------- E3: scatter src ids into CSR order ----------------
__global__ void k_scatter(const int* __restrict__ src, const int* __restrict__ dst) {
    long tid = (long)blockIdx.x * blockDim.x + threadIdx.x;
    if (tid >= (long)MM * EDGES) return;
    int m = (int)(tid / EDGES);
    int s = src[tid];
    int d = dst[tid];
    int pos = atomicAdd(&g_cursor[m * NN + d], 1);
    g_eidx[pos] = s;
}

// ---------------- E4: segment gather-reduce + mean + bias + prelu + transpose
// 16 lanes per segment, one float4 per lane. Writes g_hn[n][m][:].
__global__ void k_aggregate(const float* __restrict__ b,
                            const float* __restrict__ prelu_a) {
    long gt = (long)blockIdx.x * blockDim.x + threadIdx.x;
    long gid = gt >> 4;
    int lane = (int)(gt & 15);
    if (gid >= (long)NSEG) return;
    int m = (int)(gid / NN);
    int n = (int)(gid % NN);

    int cnt = g_count[gid];
    int end = g_cursor[gid];          // = start + cnt after scatter
    int j   = end - cnt;

    const float4* pb = (const float4*)(g_proj + (size_t)m * NN * DH);
    float4 acc = make_float4(0.f, 0.f, 0.f, 0.f);
    for (; j < end; j++) {
        int s = __ldg(&g_eidx[j]);
        float4 v = pb[(size_t)s * 16 + lane];
        acc.x += v.x; acc.y += v.y; acc.z += v.z; acc.w += v.w;
    }

    float inv   = 1.0f / fmaxf((float)cnt, 1.0f);
    float alpha = __ldg(prelu_a + m);
    float4 bv   = ((const float4*)(b + m * DH))[lane];
    float4 h;
    h.x = acc.x * inv + bv.x;  h.x = h.x > 0.f ? h.x : alpha * h.x;
    h.y = acc.y * inv + bv.y;  h.y = h.y > 0.f ? h.y : alpha * h.y;
    h.z = acc.z * inv + bv.z;  h.z = h.z > 0.f ? h.z : alpha * h.z;
    h.w = acc.w * inv + bv.w;  h.w = h.w > 0.f ? h.w : alpha * h.w;

    ((float4*)(g_hn + ((size_t)n * MM + m) * DH))[lane] = h;
}

// ---------------- K4: logits[m] = sum_n tanh(h @ fcW + fcb) . attn / N ----
// 128 threads, 256 rows/block, thread tile 8 rows (stride 32) x 16 cols.
#define HPAD 68
__global__ __launch_bounds__(128) void k_attnlogits(const float* __restrict__ fc_W,
                                                    const float* __restrict__ fc_b,
                                                    const float* __restrict__ attn) {
    extern __shared__ float dynsm[];
    float* sH = dynsm;                 // 256 x HPAD = 69632 B
    float* sW = dynsm + 256 * HPAD;    // 64 x 64   = 16384 B
    __shared__ float sPart[3];

    const int t = threadIdx.x;
    const int rg = t >> 2;
    const int cg = t & 3;
    const long p0 = (long)blockIdx.x * 256;

    if (t < 3) sPart[t] = 0.f;

    // load 256 hn rows: 4096 float4 / 128 thr = 32 each
    #pragma unroll
    for (int it = 0; it < 32; it++) {
        int idx = t + 128 * it;
        int row = idx >> 4;
        int k4  = idx & 15;
        long p  = p0 + row;
        float4 v = make_float4(0.f, 0.f, 0.f, 0.f);
        if (p < (long)NSEG)
            v = *(const float4*)(g_hn + (size_t)p * DH + k4 * 4);
        *(float4*)&sH[row * HPAD + k4 * 4] = v;
    }
    // fc_W: flat 1024 float4 / 128 thr = 8 each
    #pragma unroll
    for (int it = 0; it < 8; it++) {
        int idx = t + 128 * it;
        ((float4*)sW)[idx] = ((const float4*)fc_W)[idx];
    }
    __syncthreads();

    float2 acc[8][8];
    #pragma unroll
    for (int i = 0; i < 8; i++)
        #pragma unroll
        for (int j = 0; j < 8; j++) acc[i][j] = make_float2(0.f, 0.f);

    #pragma unroll 8
    for (int k = 0; k < DH; k++) {
        float f[8];
        #pragma unroll
        for (int i = 0; i < 8; i++) f[i] = sH[(rg + 32 * i) * HPAD + k];
        float4 w0 = *(const float4*)&sW[k * 64 + cg * 16 + 0];
        float4 w1 = *(const float4*)&sW[k * 64 + cg * 16 + 4];
        float4 w2 = *(const float4*)&sW[k * 64 + cg * 16 + 8];
        float4 w3 = *(const float4*)&sW[k * 64 + cg * 16 + 12];
        float2 wv[8] = { {w0.x,w0.y},{w0.z,w0.w},{w1.x,w1.y},{w1.z,w1.w},
                         {w2.x,w2.y},{w2.z,w2.w},{w3.x,w3.y},{w3.z,w3.w} };
        #pragma unroll
        for (int i = 0; i < 8; i++) {
            float2 fi = make_float2(f[i], f[i]);
            #pragma unroll
            for (int j = 0; j < 8; j++)
                acc[i][j] = ffma2(fi, wv[j], acc[i][j]);
        }
    }

    // epilogue: tanh, dot with attn, reduce
    const float2* fb2 = (const float2*)fc_b;
    const float2* av2 = (const float2*)attn;
    float c0 = 0.f, c1 = 0.f, c2 = 0.f;
    #pragma unroll
    for (int i = 0; i < 8; i++) {
        long p = p0 + rg + 32 * i;
        float ci = 0.f;
        #pragma unroll
        for (int j = 0; j < 8; j++) {
            float2 bb = __ldg(fb2 + cg * 8 + j);
            float2 aa = __ldg(av2 + cg * 8 + j);
            ci += tanhf(acc[i][j].x + bb.x) * aa.x
                + tanhf(acc[i][j].y + bb.y) * aa.y;
        }
        ci += __shfl_xor_sync(0xffffffffu, ci, 1);
        ci += __shfl_xor_sync(0xffffffffu, ci, 2);
        if (cg == 0 && p < (long)NSEG) {
            int mi = (int)(p % 3);
            if (mi == 0) c0 += ci; else if (mi == 1) c1 += ci; else c2 += ci;
        }
    }
    if (cg == 0) {
        atomicAdd(&sPart[0], c0);
        atomicAdd(&sPart[1], c1);
        atomicAdd(&sPart[2], c2);
    }
    __syncthreads();
    if (t < 3) atomicAdd(&g_logits[t], sPart[t] * (1.0f / (float)NN));
}

// ---------------- K5: softmax(logits) + z = sum_m beta_m * hn[:,m,:] -------
__global__ void k_combine(float* __restrict__ out) {
    const long tid = (long)blockIdx.x * blockDim.x + threadIdx.x;
    if (tid >= (long)NN * 16) return;
    const int  h4 = (int)(tid & 15);
    const long n  = tid >> 4;

    float l0 = g_logits[0], l1 = g_logits[1], l2 = g_logits[2];
    float mx = fmaxf(l0, fmaxf(l1, l2));
    float e0 = __expf(l0 - mx), e1 = __expf(l1 - mx), e2 = __expf(l2 - mx);
    float is = 1.0f / (e0 + e1 + e2);
    float b0 = e0 * is, b1 = e1 * is, b2 = e2 * is;

    const float4* r = (const float4*)(g_hn + (size_t)n * (MM * DH)) + h4;
    float4 v0 = r[0], v1 = r[16], v2 = r[32];
    float4 o;
    o.x = b0 * v0.x + b1 * v1.x + b2 * v2.x;
    o.y = b0 * v0.y + b1 * v1.y + b2 * v2.y;
    o.z = b0 * v0.z + b1 * v1.z + b2 * v2.z;
    o.w = b0 * v0.w + b1 * v1.w + b2 * v2.w;
    ((float4*)out)[tid] = o;
}

// ---------------- launcher ----------------
extern "C" void kernel_launch(void* const* d_in, const int* in_sizes, int n_in,
                              void* d_out, int out_size) {
    const float* feats   = (const float*)d_in[0];
    const int*   src     = (const int*)  d_in[1];
    const int*   dst     = (const int*)  d_in[2];
    const float* W       = (const float*)d_in[3];
    const float* b       = (const float*)d_in[4];
    const float* prelu_a = (const float*)d_in[5];
    const float* fc_W    = (const float*)d_in[6];
    const float* fc_b    = (const float*)d_in[7];
    const float* attn    = (const float*)d_in[8];
    float* out = (float*)d_out;

    void *p_cnt, *p_log;
    cudaGetSymbolAddress(&p_cnt, g_count);
    cudaGetSymbolAddress(&p_log, g_logits);
    cudaMemsetAsync(p_cnt, 0, sizeof(int) * NSEG, 0);
    cudaMemsetAsync(p_log, 0, sizeof(float) * MM, 0);

    const int attn_smem = 256 * HPAD * 4 + 64 * 64 * 4;   // 86016
    cudaFuncSetAttribute(k_attnlogits,
                         cudaFuncAttributeMaxDynamicSharedMemorySize, attn_smem);

    dim3 g1((NN + 255) / 256, MM);
    k_proj<<<g1, 128>>>(feats, W);

    const long ne = (long)MM * EDGES;
    k_hist<<<(unsigned)((ne + 255) / 256), 256>>>(dst);
    k_scanA<<<NBLK, 256>>>();
    k_scanB<<<1, 512>>>();
    k_scanC<<<NBLK, 256>>>();
    k_scatter<<<(unsigned)((ne + 255) / 256), 256>>>(src, dst);

    const long nagg = (long)NSEG * 16;
    k_aggregate<<<(unsigned)((nagg + 255) / 256), 256>>>(b, prelu_a);

    k_attnlogits<<<(unsigned)((NSEG + 255) / 256), 128, attn_smem>>>(fc_W, fc_b, attn);

    k_combine<<<(unsigned)(((long)NN * 16 + 255) / 256), 256>>>(out);
}

// round 3
// speedup vs baseline: 1.6740x; 1.1582x over previous
#include <cuda_runtime.h>
#include <cuda_fp16.h>
#include <cstdint>
#include <cstddef>

#define MM    3
#define NN    100000
#define DIN   128
#define DH    64
#define EDGES 1600000
#define NSEG  (MM * NN)                 // 300000 segments (m, dst)
#define SCAN_TILE 1024
#define NBLK  ((NSEG + SCAN_TILE - 1) / SCAN_TILE)   // 293

// ---------------- scratch (device globals; no allocations) ----------------
__device__ __half g_proj[(size_t)MM * NN * DH];  // 38.4 MB  [m][n][h] fp16
__device__ float  g_hn  [(size_t)NN * MM * DH];  // 76.8 MB  [n][m][h]
__device__ int    g_count [NSEG];                // per-(m,dst) degree
__device__ int    g_cursor[NSEG];                // within-block excl -> ends after scatter
__device__ int    g_eidx[(size_t)MM * EDGES];    // src ids sorted by (m,dst)
__device__ int    g_bsum[NBLK];
__device__ float  g_logits[MM];

// packed f32x2 FMA (FFMA2) — 2x fp32 FMA throughput, only reachable via PTX
__device__ __forceinline__ float2 ffma2(float2 a, float2 b, float2 c) {
    unsigned long long au = *reinterpret_cast<unsigned long long*>(&a);
    unsigned long long bu = *reinterpret_cast<unsigned long long*>(&b);
    unsigned long long cu = *reinterpret_cast<unsigned long long*>(&c);
    unsigned long long du;
    asm("fma.rn.f32x2 %0, %1, %2, %3;" : "=l"(du) : "l"(au), "l"(bu), "l"(cu));
    return *reinterpret_cast<float2*>(&du);
}

// ---------------- K1: proj[m] = feats[m] @ W[m]  (fp32 math, fp16 store) ---
#define FPAD 36
__global__ __launch_bounds__(128) void k_proj(const float* __restrict__ feats,
                                              const float* __restrict__ W) {
    __shared__ float sF[256 * FPAD];   // 36 KB (32-k tile, padded rows)
    __shared__ float sW[32 * 64];      // 8 KB

    const int m     = blockIdx.y;
    const int node0 = blockIdx.x * 256;
    const int t  = threadIdx.x;
    const int rg = t >> 2;
    const int cg = t & 3;

    const float* fbase = feats + (size_t)m * NN * DIN;
    const float* wbase = W     + (size_t)m * DIN * DH;

    float2 acc[8][8];
    #pragma unroll
    for (int i = 0; i < 8; i++)
        #pragma unroll
        for (int j = 0; j < 8; j++) acc[i][j] = make_float2(0.f, 0.f);

    for (int kt = 0; kt < DIN; kt += 32) {
        __syncthreads();
        #pragma unroll
        for (int it = 0; it < 16; it++) {
            int idx = t + 128 * it;
            int row = idx >> 3;
            int k4  = idx & 7;
            int gn  = node0 + row;
            float4 v = make_float4(0.f, 0.f, 0.f, 0.f);
            if (gn < NN)
                v = *(const float4*)(fbase + (size_t)gn * DIN + kt + k4 * 4);
            *(float4*)&sF[row * FPAD + k4 * 4] = v;
        }
        #pragma unroll
        for (int it = 0; it < 4; it++) {
            int idx = t + 128 * it;
            ((float4*)sW)[idx] = ((const float4*)(wbase + (size_t)kt * DH))[idx];
        }
        __syncthreads();

        #pragma unroll
        for (int k = 0; k < 32; k++) {
            float f[8];
            #pragma unroll
            for (int i = 0; i < 8; i++) f[i] = sF[(rg + 32 * i) * FPAD + k];
            float4 w0 = *(const float4*)&sW[k * 64 + cg * 16 + 0];
            float4 w1 = *(const float4*)&sW[k * 64 + cg * 16 + 4];
            float4 w2 = *(const float4*)&sW[k * 64 + cg * 16 + 8];
            float4 w3 = *(const float4*)&sW[k * 64 + cg * 16 + 12];
            float2 wv[8] = { {w0.x,w0.y},{w0.z,w0.w},{w1.x,w1.y},{w1.z,w1.w},
                             {w2.x,w2.y},{w2.z,w2.w},{w3.x,w3.y},{w3.z,w3.w} };
            #pragma unroll
            for (int i = 0; i < 8; i++) {
                float2 fi = make_float2(f[i], f[i]);
                #pragma unroll
                for (int j = 0; j < 8; j++)
                    acc[i][j] = ffma2(fi, wv[j], acc[i][j]);
            }
        }
    }

    __half* pbase = g_proj + (size_t)m * NN * DH;
    #pragma unroll
    for (int i = 0; i < 8; i++) {
        int n = node0 + rg + 32 * i;
        if (n < NN) {
            __half2* prow = (__half2*)(pbase + (size_t)n * DH + cg * 16);
            union { __half2 h[4]; uint4 u; } pk0, pk1;
            #pragma unroll
            for (int j = 0; j < 4; j++)
                pk0.h[j] = __floats2half2_rn(acc[i][j].x, acc[i][j].y);
            #pragma unroll
            for (int j = 0; j < 4; j++)
                pk1.h[j] = __floats2half2_rn(acc[i][4 + j].x, acc[i][4 + j].y);
            *(uint4*)prow       = pk0.u;
            *((uint4*)prow + 1) = pk1.u;
        }
    }
}

// ---------------- E1: histogram of (m, dst) ----------------
__global__ void k_hist(const int* __restrict__ dst) {
    int e = blockIdx.x * blockDim.x + threadIdx.x;
    if (e >= EDGES) return;
    int m = blockIdx.y;
    int d = __ldg(dst + (size_t)m * EDGES + e);
    atomicAdd(&g_count[m * NN + d], 1);
}

// ---------------- E2: two-phase exclusive scan ----------------
__global__ __launch_bounds__(256) void k_scanA() {
    __shared__ int wsum[8];
    const int t = threadIdx.x;
    const long base = (long)blockIdx.x * SCAN_TILE + t * 4;
    int v[4];
    #pragma unroll
    for (int i = 0; i < 4; i++) v[i] = (base + i < NSEG) ? g_count[base + i] : 0;
    int tsum = v[0] + v[1] + v[2] + v[3];

    const int lane = t & 31, w = t >> 5;
    int x = tsum;
    #pragma unroll
    for (int o = 1; o < 32; o <<= 1) {
        int y = __shfl_up_sync(0xffffffffu, x, o);
        if (lane >= o) x += y;
    }
    if (lane == 31) wsum[w] = x;
    __syncthreads();
    if (t < 8) {
        int y = wsum[t];
        #pragma unroll
        for (int o = 1; o < 8; o <<= 1) {
            int z = __shfl_up_sync(0x000000ffu, y, o);
            if (t >= o) y += z;
        }
        wsum[t] = y;
    }
    __syncthreads();
    int run = ((w > 0) ? wsum[w - 1] : 0) + x - tsum;   // exclusive, within block
    #pragma unroll
    for (int i = 0; i < 4; i++) {
        if (base + i < NSEG) g_cursor[base + i] = run;
        run += v[i];
    }
    if (t == 255) g_bsum[blockIdx.x] = wsum[7];
}

__global__ __launch_bounds__(512) void k_scanB() {
    __shared__ int a[512];
    const int t = threadIdx.x;
    int v = (t < NBLK) ? g_bsum[t] : 0;
    a[t] = v;
    __syncthreads();
    #pragma unroll
    for (int o = 1; o < 512; o <<= 1) {
        int x = (t >= o) ? a[t - o] : 0;
        __syncthreads();
        a[t] += x;
        __syncthreads();
    }
    if (t < NBLK) g_bsum[t] = a[t] - v;    // exclusive block bases
}

// ---------------- E3: scatter src ids into CSR order ----------------
__global__ void k_scatter(const int* __restrict__ src, const int* __restrict__ dst) {
    int e = blockIdx.x * blockDim.x + threadIdx.x;
    if (e >= EDGES) return;
    int m = blockIdx.y;
    int s = __ldg(src + (size_t)m * EDGES + e);
    int d = __ldg(dst + (size_t)m * EDGES + e);
    int seg = m * NN + d;
    int pos = atomicAdd(&g_cursor[seg], 1) + __ldg(&g_bsum[seg >> 10]);
    g_eidx[pos] = s;
}

// ---------------- E4: gather-reduce + mean + bias + prelu + transpose ------
// 8 lanes per segment; each lane owns 8 h-channels (one uint4 of fp16).
__global__ void k_aggregate(const float* __restrict__ b,
                            const float* __restrict__ prelu_a) {
    long gt  = (long)blockIdx.x * blockDim.x + threadIdx.x;
    long gid = gt >> 3;
    int lane = (int)(gt & 7);
    if (gid >= (long)NSEG) return;
    int m = (int)(gid / NN);
    int n = (int)(gid % NN);

    int cnt = g_count[gid];
    int end = g_cursor[gid] + __ldg(&g_bsum[gid >> 10]);  // cursor == start+cnt
    int j   = end - cnt;

    const uint4* pb = (const uint4*)g_proj + (size_t)m * NN * 8;
    float acc[8] = {0.f, 0.f, 0.f, 0.f, 0.f, 0.f, 0.f, 0.f};
    for (; j < end; j++) {
        int s = __ldg(&g_eidx[j]);
        uint4 v = __ldg(&pb[(size_t)s * 8 + lane]);
        float2 f0 = __half22float2(*(__half2*)&v.x);
        float2 f1 = __half22float2(*(__half2*)&v.y);
        float2 f2 = __half22float2(*(__half2*)&v.z);
        float2 f3 = __half22float2(*(__half2*)&v.w);
        acc[0] += f0.x; acc[1] += f0.y;
        acc[2] += f1.x; acc[3] += f1.y;
        acc[4] += f2.x; acc[5] += f2.y;
        acc[6] += f3.x; acc[7] += f3.y;
    }

    float inv   = 1.0f / fmaxf((float)cnt, 1.0f);
    float alpha = __ldg(prelu_a + m);
    const float* bp = b + m * DH + lane * 8;
    float* op = g_hn + ((size_t)n * MM + m) * DH + lane * 8;
    float4 o0, o1;
    float* oo[8] = {&o0.x,&o0.y,&o0.z,&o0.w,&o1.x,&o1.y,&o1.z,&o1.w};
    #pragma unroll
    for (int c = 0; c < 8; c++) {
        float h = acc[c] * inv + __ldg(bp + c);
        *oo[c] = h > 0.f ? h : alpha * h;
    }
    *(float4*)op       = o0;
    *(float4*)(op + 4) = o1;
}

// ---------------- K4: logits[m] = sum_n tanh(h @ fcW + fcb) . attn / N ----
#define HPAD 68
__global__ __launch_bounds__(128) void k_attnlogits(const float* __restrict__ fc_W,
                                                    const float* __restrict__ fc_b,
                                                    const float* __restrict__ attn) {
    extern __shared__ float dynsm[];
    float* sH = dynsm;                 // 256 x HPAD
    float* sW = dynsm + 256 * HPAD;    // 64 x 64
    __shared__ float sPart[3];

    const int t = threadIdx.x;
    const int rg = t >> 2;
    const int cg = t & 3;
    const long p0 = (long)blockIdx.x * 256;

    if (t < 3) sPart[t] = 0.f;

    #pragma unroll
    for (int it = 0; it < 32; it++) {
        int idx = t + 128 * it;
        int row = idx >> 4;
        int k4  = idx & 15;
        long p  = p0 + row;
        float4 v = make_float4(0.f, 0.f, 0.f, 0.f);
        if (p < (long)NSEG)
            v = *(const float4*)(g_hn + (size_t)p * DH + k4 * 4);
        *(float4*)&sH[row * HPAD + k4 * 4] = v;
    }
    #pragma unroll
    for (int it = 0; it < 8; it++) {
        int idx = t + 128 * it;
        ((float4*)sW)[idx] = ((const float4*)fc_W)[idx];
    }
    __syncthreads();

    float2 acc[8][8];
    #pragma unroll
    for (int i = 0; i < 8; i++)
        #pragma unroll
        for (int j = 0; j < 8; j++) acc[i][j] = make_float2(0.f, 0.f);

    #pragma unroll 8
    for (int k = 0; k < DH; k++) {
        float f[8];
        #pragma unroll
        for (int i = 0; i < 8; i++) f[i] = sH[(rg + 32 * i) * HPAD + k];
        float4 w0 = *(const float4*)&sW[k * 64 + cg * 16 + 0];
        float4 w1 = *(const float4*)&sW[k * 64 + cg * 16 + 4];
        float4 w2 = *(const float4*)&sW[k * 64 + cg * 16 + 8];
        float4 w3 = *(const float4*)&sW[k * 64 + cg * 16 + 12];
        float2 wv[8] = { {w0.x,w0.y},{w0.z,w0.w},{w1.x,w1.y},{w1.z,w1.w},
                         {w2.x,w2.y},{w2.z,w2.w},{w3.x,w3.y},{w3.z,w3.w} };
        #pragma unroll
        for (int i = 0; i < 8; i++) {
            float2 fi = make_float2(f[i], f[i]);
            #pragma unroll
            for (int j = 0; j < 8; j++)
                acc[i][j] = ffma2(fi, wv[j], acc[i][j]);
        }
    }

    const float2* fb2 = (const float2*)fc_b;
    const float2* av2 = (const float2*)attn;
    float c0 = 0.f, c1 = 0.f, c2 = 0.f;
    #pragma unroll
    for (int i = 0; i < 8; i++) {
        long p = p0 + rg + 32 * i;
        float ci = 0.f;
        #pragma unroll
        for (int j = 0; j < 8; j++) {
            float2 bb = __ldg(fb2 + cg * 8 + j);
            float2 aa = __ldg(av2 + cg * 8 + j);
            ci += tanhf(acc[i][j].x + bb.x) * aa.x
                + tanhf(acc[i][j].y + bb.y) * aa.y;
        }
        ci += __shfl_xor_sync(0xffffffffu, ci, 1);
        ci += __shfl_xor_sync(0xffffffffu, ci, 2);
        if (cg == 0 && p < (long)NSEG) {
            int mi = (int)(p % 3);
            if (mi == 0) c0 += ci; else if (mi == 1) c1 += ci; else c2 += ci;
        }
    }
    if (cg == 0) {
        atomicAdd(&sPart[0], c0);
        atomicAdd(&sPart[1], c1);
        atomicAdd(&sPart[2], c2);
    }
    __syncthreads();
    if (t < 3) atomicAdd(&g_logits[t], sPart[t] * (1.0f / (float)NN));
}

// ---------------- K5: softmax(logits) + z = sum_m beta_m * hn[:,m,:] -------
__global__ void k_combine(float* __restrict__ out) {
    const long tid = (long)blockIdx.x * blockDim.x + threadIdx.x;
    if (tid >= (long)NN * 16) return;
    const int  h4 = (int)(tid & 15);
    const long n  = tid >> 4;

    float l0 = g_logits[0], l1 = g_logits[1], l2 = g_logits[2];
    float mx = fmaxf(l0, fmaxf(l1, l2));
    float e0 = __expf(l0 - mx), e1 = __expf(l1 - mx), e2 = __expf(l2 - mx);
    float is = 1.0f / (e0 + e1 + e2);
    float b0 = e0 * is, b1 = e1 * is, b2 = e2 * is;

    const float4* r = (const float4*)(g_hn + (size_t)n * (MM * DH)) + h4;
    float4 v0 = r[0], v1 = r[16], v2 = r[32];
    float4 o;
    o.x = b0 * v0.x + b1 * v1.x + b2 * v2.x;
    o.y = b0 * v0.y + b1 * v1.y + b2 * v2.y;
    o.z = b0 * v0.z + b1 * v1.z + b2 * v2.z;
    o.w = b0 * v0.w + b1 * v1.w + b2 * v2.w;
    ((float4*)out)[tid] = o;
}

// ---------------- launcher (fork-join: sort pipeline ∥ proj) ----------------
static cudaStream_t s_side = nullptr;
static cudaEvent_t  s_evFork = nullptr, s_evJoin = nullptr;

extern "C" void kernel_launch(void* const* d_in, const int* in_sizes, int n_in,
                              void* d_out, int out_size) {
    const float* feats   = (const float*)d_in[0];
    const int*   src     = (const int*)  d_in[1];
    const int*   dst     = (const int*)  d_in[2];
    const float* W       = (const float*)d_in[3];
    const float* b       = (const float*)d_in[4];
    const float* prelu_a = (const float*)d_in[5];
    const float* fc_W    = (const float*)d_in[6];
    const float* fc_b    = (const float*)d_in[7];
    const float* attn    = (const float*)d_in[8];
    float* out = (float*)d_out;

    if (!s_side) {
        cudaStreamCreateWithFlags(&s_side, cudaStreamNonBlocking);
        cudaEventCreateWithFlags(&s_evFork, cudaEventDisableTiming);
        cudaEventCreateWithFlags(&s_evJoin, cudaEventDisableTiming);
    }

    void *p_cnt, *p_log;
    cudaGetSymbolAddress(&p_cnt, g_count);
    cudaGetSymbolAddress(&p_log, g_logits);
    cudaMemsetAsync(p_cnt, 0, sizeof(int) * NSEG, 0);
    cudaMemsetAsync(p_log, 0, sizeof(float) * MM, 0);

    const int attn_smem = 256 * HPAD * 4 + 64 * 64 * 4;
    cudaFuncSetAttribute(k_attnlogits,
                         cudaFuncAttributeMaxDynamicSharedMemorySize, attn_smem);

    // fork: sort pipeline on side stream
    cudaEventRecord(s_evFork, 0);
    cudaStreamWaitEvent(s_side, s_evFork, 0);

    dim3 ge((EDGES + 255) / 256, MM);
    k_hist   <<<ge, 256, 0, s_side>>>(dst);
    k_scanA  <<<NBLK, 256, 0, s_side>>>();
    k_scanB  <<<1, 512, 0, s_side>>>();
    k_scatter<<<ge, 256, 0, s_side>>>(src, dst);
    cudaEventRecord(s_evJoin, s_side);

    // main stream: projection GEMM
    dim3 g1((NN + 255) / 256, MM);
    k_proj<<<g1, 128>>>(feats, W);

    // join, then aggregate -> attnlogits -> combine
    cudaStreamWaitEvent(0, s_evJoin, 0);

    const long nagg = (long)NSEG * 8;
    k_aggregate<<<(unsigned)((nagg + 255) / 256), 256>>>(b, prelu_a);

    k_attnlogits<<<(unsigned)((NSEG + 255) / 256), 128, attn_smem>>>(fc_W, fc_b, attn);

    k_combine<<<(unsigned)(((long)NN * 16 + 255) / 256), 256>>>(out);
}

// round 4
// speedup vs baseline: 1.7240x; 1.0298x over previous
#include <cuda_runtime.h>
#include <cuda_fp16.h>
#include <cstdint>
#include <cstddef>

#define MM    3
#define NN    100000
#define DIN   128
#define DH    64
#define EDGES 1600000
#define NSEG  (MM * NN)                 // 300000 segments (m, dst)
#define SCAN_TILE 1024
#define NBLK  ((NSEG + SCAN_TILE - 1) / SCAN_TILE)   // 293

// ---------------- scratch (device globals; no allocations) ----------------
__device__ __half g_proj[(size_t)MM * NN * DH];  // 38.4 MB [m][n][h] fp16
__device__ __half g_hn  [(size_t)NN * MM * DH];  // 38.4 MB [n][m][h] fp16
__device__ int    g_count [NSEG];                // per-(m,dst) degree
__device__ int    g_cursor[NSEG];                // within-block exclusive starts
__device__ int    g_eidx[(size_t)MM * EDGES];    // src ids sorted by (m,dst)
__device__ unsigned short g_rank[(size_t)MM * EDGES]; // rank of edge in its segment
__device__ int    g_bsum[NBLK];
__device__ float  g_logits[MM];

// packed f32x2 FMA (FFMA2) — 2x fp32 FMA throughput, only reachable via PTX
__device__ __forceinline__ float2 ffma2(float2 a, float2 b, float2 c) {
    unsigned long long au = *reinterpret_cast<unsigned long long*>(&a);
    unsigned long long bu = *reinterpret_cast<unsigned long long*>(&b);
    unsigned long long cu = *reinterpret_cast<unsigned long long*>(&c);
    unsigned long long du;
    asm("fma.rn.f32x2 %0, %1, %2, %3;" : "=l"(du) : "l"(au), "l"(bu), "l"(cu));
    return *reinterpret_cast<float2*>(&du);
}

// ---------------- K1: proj[m] = feats[m] @ W[m]  (fp32 math, fp16 store) ---
#define FPAD 36
__global__ __launch_bounds__(128) void k_proj(const float* __restrict__ feats,
                                              const float* __restrict__ W) {
    __shared__ float sF[256 * FPAD];   // 36 KB
    __shared__ float sW[32 * 64];      // 8 KB

    const int m     = blockIdx.y;
    const int node0 = blockIdx.x * 256;
    const int t  = threadIdx.x;
    const int rg = t >> 2;
    const int cg = t & 3;

    const float* fbase = feats + (size_t)m * NN * DIN;
    const float* wbase = W     + (size_t)m * DIN * DH;

    float2 acc[8][8];
    #pragma unroll
    for (int i = 0; i < 8; i++)
        #pragma unroll
        for (int j = 0; j < 8; j++) acc[i][j] = make_float2(0.f, 0.f);

    for (int kt = 0; kt < DIN; kt += 32) {
        __syncthreads();
        #pragma unroll
        for (int it = 0; it < 16; it++) {
            int idx = t + 128 * it;
            int row = idx >> 3;
            int k4  = idx & 7;
            int gn  = node0 + row;
            float4 v = make_float4(0.f, 0.f, 0.f, 0.f);
            if (gn < NN)
                v = *(const float4*)(fbase + (size_t)gn * DIN + kt + k4 * 4);
            *(float4*)&sF[row * FPAD + k4 * 4] = v;
        }
        #pragma unroll
        for (int it = 0; it < 4; it++) {
            int idx = t + 128 * it;
            ((float4*)sW)[idx] = ((const float4*)(wbase + (size_t)kt * DH))[idx];
        }
        __syncthreads();

        #pragma unroll
        for (int k = 0; k < 32; k++) {
            float f[8];
            #pragma unroll
            for (int i = 0; i < 8; i++) f[i] = sF[(rg + 32 * i) * FPAD + k];
            float4 w0 = *(const float4*)&sW[k * 64 + cg * 16 + 0];
            float4 w1 = *(const float4*)&sW[k * 64 + cg * 16 + 4];
            float4 w2 = *(const float4*)&sW[k * 64 + cg * 16 + 8];
            float4 w3 = *(const float4*)&sW[k * 64 + cg * 16 + 12];
            float2 wv[8] = { {w0.x,w0.y},{w0.z,w0.w},{w1.x,w1.y},{w1.z,w1.w},
                             {w2.x,w2.y},{w2.z,w2.w},{w3.x,w3.y},{w3.z,w3.w} };
            #pragma unroll
            for (int i = 0; i < 8; i++) {
                float2 fi = make_float2(f[i], f[i]);
                #pragma unroll
                for (int j = 0; j < 8; j++)
                    acc[i][j] = ffma2(fi, wv[j], acc[i][j]);
            }
        }
    }

    __half* pbase = g_proj + (size_t)m * NN * DH;
    #pragma unroll
    for (int i = 0; i < 8; i++) {
        int n = node0 + rg + 32 * i;
        if (n < NN) {
            __half2* prow = (__half2*)(pbase + (size_t)n * DH + cg * 16);
            union { __half2 h[4]; uint4 u; } pk0, pk1;
            #pragma unroll
            for (int j = 0; j < 4; j++)
                pk0.h[j] = __floats2half2_rn(acc[i][j].x, acc[i][j].y);
            #pragma unroll
            for (int j = 0; j < 4; j++)
                pk1.h[j] = __floats2half2_rn(acc[i][4 + j].x, acc[i][4 + j].y);
            *(uint4*)prow       = pk0.u;
            *((uint4*)prow + 1) = pk1.u;
        }
    }
}

// ---------------- E1: histogram of (m, dst) + per-edge rank ----------------
__global__ void k_hist(const int* __restrict__ dst) {
    int e = blockIdx.x * blockDim.x + threadIdx.x;
    if (e >= EDGES) return;
    int m = blockIdx.y;
    int d = __ldg(dst + (size_t)m * EDGES + e);
    int r = atomicAdd(&g_count[m * NN + d], 1);
    g_rank[(size_t)m * EDGES + e] = (unsigned short)r;
}

// ---------------- E2: two-phase exclusive scan ----------------
__global__ __launch_bounds__(256) void k_scanA() {
    __shared__ int wsum[8];
    const int t = threadIdx.x;
    const long base = (long)blockIdx.x * SCAN_TILE + t * 4;
    int v[4];
    #pragma unroll
    for (int i = 0; i < 4; i++) v[i] = (base + i < NSEG) ? g_count[base + i] : 0;
    int tsum = v[0] + v[1] + v[2] + v[3];

    const int lane = t & 31, w = t >> 5;
    int x = tsum;
    #pragma unroll
    for (int o = 1; o < 32; o <<= 1) {
        int y = __shfl_up_sync(0xffffffffu, x, o);
        if (lane >= o) x += y;
    }
    if (lane == 31) wsum[w] = x;
    __syncthreads();
    if (t < 8) {
        int y = wsum[t];
        #pragma unroll
        for (int o = 1; o < 8; o <<= 1) {
            int z = __shfl_up_sync(0x000000ffu, y, o);
            if (t >= o) y += z;
        }
        wsum[t] = y;
    }
    __syncthreads();
    int run = ((w > 0) ? wsum[w - 1] : 0) + x - tsum;   // exclusive, within block
    #pragma unroll
    for (int i = 0; i < 4; i++) {
        if (base + i < NSEG) g_cursor[base + i] = run;
        run += v[i];
    }
    if (t == 255) g_bsum[blockIdx.x] = wsum[7];
}

__global__ __launch_bounds__(512) void k_scanB() {
    __shared__ int a[512];
    const int t = threadIdx.x;
    int v = (t < NBLK) ? g_bsum[t] : 0;
    a[t] = v;
    __syncthreads();
    #pragma unroll
    for (int o = 1; o < 512; o <<= 1) {
        int x = (t >= o) ? a[t - o] : 0;
        __syncthreads();
        a[t] += x;
        __syncthreads();
    }
    if (t < NBLK) g_bsum[t] = a[t] - v;    // exclusive block bases
}

// ---------------- E3: scatter src ids into CSR order (no atomics) ----------
__global__ void k_scatter(const int* __restrict__ src, const int* __restrict__ dst) {
    int e = blockIdx.x * blockDim.x + threadIdx.x;
    if (e >= EDGES) return;
    int m = blockIdx.y;
    int s   = __ldg(src + (size_t)m * EDGES + e);
    int d   = __ldg(dst + (size_t)m * EDGES + e);
    int rk  = (int)__ldg(&g_rank[(size_t)m * EDGES + e]);
    int seg = m * NN + d;
    int pos = __ldg(&g_cursor[seg]) + __ldg(&g_bsum[seg >> 10]) + rk;
    g_eidx[pos] = s;
}

// ---------------- E4: gather-reduce + mean + bias + prelu + transpose ------
// 8 lanes per segment; each lane owns 8 h-channels (one uint4 of fp16).
__global__ void k_aggregate(const float* __restrict__ b,
                            const float* __restrict__ prelu_a) {
    long gt  = (long)blockIdx.x * blockDim.x + threadIdx.x;
    long gid = gt >> 3;
    int lane = (int)(gt & 7);
    if (gid >= (long)NSEG) return;
    int m = (int)(gid / NN);
    int n = (int)(gid % NN);

    int cnt   = g_count[gid];
    int start = g_cursor[gid] + __ldg(&g_bsum[gid >> 10]);
    int end   = start + cnt;

    const uint4* pb = (const uint4*)g_proj + (size_t)m * NN * 8;
    float acc[8] = {0.f, 0.f, 0.f, 0.f, 0.f, 0.f, 0.f, 0.f};
    for (int j = start; j < end; j++) {
        int s = __ldg(&g_eidx[j]);
        uint4 v = __ldg(&pb[(size_t)s * 8 + lane]);
        float2 f0 = __half22float2(*(__half2*)&v.x);
        float2 f1 = __half22float2(*(__half2*)&v.y);
        float2 f2 = __half22float2(*(__half2*)&v.z);
        float2 f3 = __half22float2(*(__half2*)&v.w);
        acc[0] += f0.x; acc[1] += f0.y;
        acc[2] += f1.x; acc[3] += f1.y;
        acc[4] += f2.x; acc[5] += f2.y;
        acc[6] += f3.x; acc[7] += f3.y;
    }

    float inv   = 1.0f / fmaxf((float)cnt, 1.0f);
    float alpha = __ldg(prelu_a + m);
    const float* bp = b + m * DH + lane * 8;
    float h[8];
    #pragma unroll
    for (int c = 0; c < 8; c++) {
        float x = acc[c] * inv + __ldg(bp + c);
        h[c] = x > 0.f ? x : alpha * x;
    }
    union { __half2 p[4]; uint4 u; } pk;
    #pragma unroll
    for (int c = 0; c < 4; c++)
        pk.p[c] = __floats2half2_rn(h[2*c], h[2*c+1]);
    ((uint4*)(g_hn + ((size_t)n * MM + m) * DH))[lane] = pk.u;
}

// ---------------- K4: logits[m] = sum_n tanh(h @ fcW + fcb) . attn / N ----
#define HPAD 68
__global__ __launch_bounds__(128) void k_attnlogits(const float* __restrict__ fc_W,
                                                    const float* __restrict__ fc_b,
                                                    const float* __restrict__ attn) {
    extern __shared__ float dynsm[];
    float* sH = dynsm;                 // 256 x HPAD
    float* sW = dynsm + 256 * HPAD;    // 64 x 64
    __shared__ float sPart[3];

    const int t = threadIdx.x;
    const int rg = t >> 2;
    const int cg = t & 3;
    const long p0 = (long)blockIdx.x * 256;

    if (t < 3) sPart[t] = 0.f;

    // load 256 fp16 rows: 2048 uint4 (8 halfs each) / 128 thr = 16 each
    #pragma unroll
    for (int it = 0; it < 16; it++) {
        int idx = t + 128 * it;
        int row = idx >> 3;
        int k8  = idx & 7;
        long p  = p0 + row;
        uint4 v = make_uint4(0u, 0u, 0u, 0u);
        if (p < (long)NSEG)
            v = *((const uint4*)(g_hn + (size_t)p * DH) + k8);
        float* dstp = &sH[row * HPAD + k8 * 8];
        float2 f0 = __half22float2(*(__half2*)&v.x);
        float2 f1 = __half22float2(*(__half2*)&v.y);
        float2 f2 = __half22float2(*(__half2*)&v.z);
        float2 f3 = __half22float2(*(__half2*)&v.w);
        dstp[0] = f0.x; dstp[1] = f0.y; dstp[2] = f1.x; dstp[3] = f1.y;
        dstp[4] = f2.x; dstp[5] = f2.y; dstp[6] = f3.x; dstp[7] = f3.y;
    }
    #pragma unroll
    for (int it = 0; it < 8; it++) {
        int idx = t + 128 * it;
        ((float4*)sW)[idx] = ((const float4*)fc_W)[idx];
    }
    __syncthreads();

    float2 acc[8][8];
    #pragma unroll
    for (int i = 0; i < 8; i++)
        #pragma unroll
        for (int j = 0; j < 8; j++) acc[i][j] = make_float2(0.f, 0.f);

    #pragma unroll 8
    for (int k = 0; k < DH; k++) {
        float f[8];
        #pragma unroll
        for (int i = 0; i < 8; i++) f[i] = sH[(rg + 32 * i) * HPAD + k];
        float4 w0 = *(const float4*)&sW[k * 64 + cg * 16 + 0];
        float4 w1 = *(const float4*)&sW[k * 64 + cg * 16 + 4];
        float4 w2 = *(const float4*)&sW[k * 64 + cg * 16 + 8];
        float4 w3 = *(const float4*)&sW[k * 64 + cg * 16 + 12];
        float2 wv[8] = { {w0.x,w0.y},{w0.z,w0.w},{w1.x,w1.y},{w1.z,w1.w},
                         {w2.x,w2.y},{w2.z,w2.w},{w3.x,w3.y},{w3.z,w3.w} };
        #pragma unroll
        for (int i = 0; i < 8; i++) {
            float2 fi = make_float2(f[i], f[i]);
            #pragma unroll
            for (int j = 0; j < 8; j++)
                acc[i][j] = ffma2(fi, wv[j], acc[i][j]);
        }
    }

    const float2* fb2 = (const float2*)fc_b;
    const float2* av2 = (const float2*)attn;
    float c0 = 0.f, c1 = 0.f, c2 = 0.f;
    #pragma unroll
    for (int i = 0; i < 8; i++) {
        long p = p0 + rg + 32 * i;
        float ci = 0.f;
        #pragma unroll
        for (int j = 0; j < 8; j++) {
            float2 bb = __ldg(fb2 + cg * 8 + j);
            float2 aa = __ldg(av2 + cg * 8 + j);
            ci += tanhf(acc[i][j].x + bb.x) * aa.x
                + tanhf(acc[i][j].y + bb.y) * aa.y;
        }
        ci += __shfl_xor_sync(0xffffffffu, ci, 1);
        ci += __shfl_xor_sync(0xffffffffu, ci, 2);
        if (cg == 0 && p < (long)NSEG) {
            int mi = (int)(p % 3);
            if (mi == 0) c0 += ci; else if (mi == 1) c1 += ci; else c2 += ci;
        }
    }
    if (cg == 0) {
        atomicAdd(&sPart[0], c0);
        atomicAdd(&sPart[1], c1);
        atomicAdd(&sPart[2], c2);
    }
    __syncthreads();
    if (t < 3) atomicAdd(&g_logits[t], sPart[t] * (1.0f / (float)NN));
}

// ---------------- K5: softmax(logits) + z = sum_m beta_m * hn[:,m,:] -------
// thread = (n, q); q indexes 8 channels (one uint4 of fp16 per m).
__global__ void k_combine(float* __restrict__ out) {
    const long tid = (long)blockIdx.x * blockDim.x + threadIdx.x;
    if (tid >= (long)NN * 8) return;
    const int  q = (int)(tid & 7);
    const long n = tid >> 3;

    float l0 = g_logits[0], l1 = g_logits[1], l2 = g_logits[2];
    float mx = fmaxf(l0, fmaxf(l1, l2));
    float e0 = __expf(l0 - mx), e1 = __expf(l1 - mx), e2 = __expf(l2 - mx);
    float is = 1.0f / (e0 + e1 + e2);
    float b0 = e0 * is, b1 = e1 * is, b2 = e2 * is;

    const uint4* r = (const uint4*)(g_hn + (size_t)n * (MM * DH)) + q;
    uint4 u0 = __ldg(r), u1 = __ldg(r + 8), u2 = __ldg(r + 16);

    float o[8];
    #pragma unroll
    for (int c = 0; c < 4; c++) {
        float2 f0 = __half22float2(((const __half2*)&u0)[c]);
        float2 f1 = __half22float2(((const __half2*)&u1)[c]);
        float2 f2 = __half22float2(((const __half2*)&u2)[c]);
        o[2*c]   = b0 * f0.x + b1 * f1.x + b2 * f2.x;
        o[2*c+1] = b0 * f0.y + b1 * f1.y + b2 * f2.y;
    }
    float* op = out + (size_t)n * DH + q * 8;
    *(float4*)op       = make_float4(o[0], o[1], o[2], o[3]);
    *(float4*)(op + 4) = make_float4(o[4], o[5], o[6], o[7]);
}

// ---------------- launcher (fork-join: sort pipeline ∥ proj) ----------------
static cudaStream_t s_side = nullptr;
static cudaEvent_t  s_evFork = nullptr, s_evJoin = nullptr;

extern "C" void kernel_launch(void* const* d_in, const int* in_sizes, int n_in,
                              void* d_out, int out_size) {
    const float* feats   = (const float*)d_in[0];
    const int*   src     = (const int*)  d_in[1];
    const int*   dst     = (const int*)  d_in[2];
    const float* W       = (const float*)d_in[3];
    const float* b       = (const float*)d_in[4];
    const float* prelu_a = (const float*)d_in[5];
    const float* fc_W    = (const float*)d_in[6];
    const float* fc_b    = (const float*)d_in[7];
    const float* attn    = (const float*)d_in[8];
    float* out = (float*)d_out;

    if (!s_side) {
        cudaStreamCreateWithFlags(&s_side, cudaStreamNonBlocking);
        cudaEventCreateWithFlags(&s_evFork, cudaEventDisableTiming);
        cudaEventCreateWithFlags(&s_evJoin, cudaEventDisableTiming);
    }

    void *p_cnt, *p_log;
    cudaGetSymbolAddress(&p_cnt, g_count);
    cudaGetSymbolAddress(&p_log, g_logits);

    const int attn_smem = 256 * HPAD * 4 + 64 * 64 * 4;
    cudaFuncSetAttribute(k_attnlogits,
                         cudaFuncAttributeMaxDynamicSharedMemorySize, attn_smem);

    // fork: sort pipeline on side stream
    cudaEventRecord(s_evFork, 0);
    cudaStreamWaitEvent(s_side, s_evFork, 0);

    cudaMemsetAsync(p_cnt, 0, sizeof(int) * NSEG, s_side);
    dim3 ge((EDGES + 255) / 256, MM);
    k_hist   <<<ge, 256, 0, s_side>>>(dst);
    k_scanA  <<<NBLK, 256, 0, s_side>>>();
    k_scanB  <<<1, 512, 0, s_side>>>();
    k_scatter<<<ge, 256, 0, s_side>>>(src, dst);
    cudaEventRecord(s_evJoin, s_side);

    // main stream: projection GEMM (+ logits clear)
    cudaMemsetAsync(p_log, 0, sizeof(float) * MM, 0);
    dim3 g1((NN + 255) / 256, MM);
    k_proj<<<g1, 128>>>(feats, W);

    // join, then aggregate -> attnlogits -> combine
    cudaStreamWaitEvent(0, s_evJoin, 0);

    const long nagg = (long)NSEG * 8;
    k_aggregate<<<(unsigned)((nagg + 255) / 256), 256>>>(b, prelu_a);

    k_attnlogits<<<(unsigned)((NSEG + 255) / 256), 128, attn_smem>>>(fc_W, fc_b, attn);

    k_combine<<<(unsigned)(((long)NN * 8 + 255) / 256), 256>>>(out);
}